// round 15
// baseline (speedup 1.0000x reference)
#include <cuda_runtime.h>
#include <cstdint>
#include <cfloat>
#include <math.h>

#define M_TOT 16384
#define D_IN  1024
#define E_DIM 512
#define K_CB  4096
#define VK    1536              // 3 x 512 virtual contraction (3xTF32)
#define NSL   48                // 32-e slices per chunk
#define NCHUNK 16               // k chunks of 256
#define GTOT  (NCHUNK * NSL)    // 768

__device__ float g_xn[M_TOT * E_DIM];
__device__ float g_xv[(size_t)M_TOT * VK];   // [hi|lo|hi], e-permuted within 8
__device__ float g_cv[(size_t)K_CB * VK];    // [hi|hi|lo], e-permuted within 8
__device__ float g_cnn[K_CB];

// ---- helpers ----
__device__ __forceinline__ void cp_async16(uint32_t s, const void* g) {
    asm volatile("cp.async.cg.shared.global [%0], [%1], 16;" :: "r"(s), "l"(g) : "memory");
}
__device__ __forceinline__ void cp_commit() {
    asm volatile("cp.async.commit_group;" ::: "memory");
}
template <int N> __device__ __forceinline__ void cp_wait() {
    asm volatile("cp.async.wait_group %0;" :: "n"(N) : "memory");
}
__device__ __forceinline__ float tf32r(float x) {
    uint32_t r; asm("cvt.rna.tf32.f32 %0, %1;" : "=r"(r) : "f"(x));
    return __uint_as_float(r);
}
// within-8 permutation: position (e&3)*2 + ((e&7)>>2) holds e
__device__ __forceinline__ int st_perm(int e) {
    return (e & ~7) + ((e & 3) * 2 + ((e & 7) >> 2));
}
__device__ __forceinline__ void mma_tf32(float* c, uint32_t a0, uint32_t a1,
                                         uint32_t a2, uint32_t a3,
                                         uint32_t b0, uint32_t b1) {
    asm volatile("mma.sync.aligned.m16n8k8.row.col.f32.tf32.tf32.f32 "
                 "{%0,%1,%2,%3}, {%4,%5,%6,%7}, {%8,%9}, {%0,%1,%2,%3};"
                 : "+f"(c[0]), "+f"(c[1]), "+f"(c[2]), "+f"(c[3])
                 : "r"(a0), "r"(a1), "r"(a2), "r"(a3), "r"(b0), "r"(b1));
}

// ---------------------------------------------------------------------------
// Kernel 1: projection GEMM (known-good scalar, R11)
// ---------------------------------------------------------------------------
__global__ void proj_gemm_kernel(const float* __restrict__ X, const float* __restrict__ W) {
    __shared__ float As[32 * 132];
    __shared__ float Bs[32 * 64];
    const int tx = threadIdx.x & 15, ty = threadIdx.x >> 4;
    const int m0 = blockIdx.y * 128, n0 = blockIdx.x * 64;
    float acc[8][4];
    #pragma unroll
    for (int i = 0; i < 8; i++)
        #pragma unroll
        for (int j = 0; j < 4; j++) acc[i][j] = 0.0f;
    for (int kt = 0; kt < D_IN; kt += 32) {
        #pragma unroll
        for (int t = 0; t < 4; t++) {
            int f = threadIdx.x + t * 256, row = f >> 3, c4 = f & 7;
            float4 v = *(const float4*)(X + (size_t)(m0 + row) * D_IN + kt + c4 * 4);
            As[(c4 * 4 + 0) * 132 + row] = v.x; As[(c4 * 4 + 1) * 132 + row] = v.y;
            As[(c4 * 4 + 2) * 132 + row] = v.z; As[(c4 * 4 + 3) * 132 + row] = v.w;
        }
        #pragma unroll
        for (int t = 0; t < 2; t++) {
            int f = threadIdx.x + t * 256, k = f >> 4, c4 = f & 15;
            *(float4*)(Bs + k * 64 + c4 * 4) =
                *(const float4*)(W + (size_t)(kt + k) * E_DIM + n0 + c4 * 4);
        }
        __syncthreads();
        #pragma unroll
        for (int k = 0; k < 32; k++) {
            float4 a0 = *(const float4*)(As + k * 132 + ty * 8);
            float4 a1 = *(const float4*)(As + k * 132 + ty * 8 + 4);
            float4 b  = *(const float4*)(Bs + k * 64 + tx * 4);
            float a[8] = {a0.x, a0.y, a0.z, a0.w, a1.x, a1.y, a1.z, a1.w};
            float bb[4] = {b.x, b.y, b.z, b.w};
            #pragma unroll
            for (int i = 0; i < 8; i++)
                #pragma unroll
                for (int j = 0; j < 4; j++) acc[i][j] = fmaf(a[i], bb[j], acc[i][j]);
        }
        __syncthreads();
    }
    #pragma unroll
    for (int i = 0; i < 8; i++)
        *(float4*)(g_xn + (size_t)(m0 + ty * 8 + i) * E_DIM + n0 + tx * 4) =
            make_float4(acc[i][0], acc[i][1], acc[i][2], acc[i][3]);
}

// normalize x + 3xTF32 split -> g_xv [hi|lo|hi], permuted
__global__ void norm_split_x_kernel() {
    const int row = blockIdx.x;
    const int e0 = threadIdx.x * 4;
    float4 v = *(const float4*)(g_xn + (size_t)row * E_DIM + e0);
    float s = v.x * v.x + v.y * v.y + v.z * v.z + v.w * v.w;
    #pragma unroll
    for (int o = 16; o > 0; o >>= 1) s += __shfl_xor_sync(0xFFFFFFFFu, s, o);
    __shared__ float ws[4];
    if ((threadIdx.x & 31) == 0) ws[threadIdx.x >> 5] = s;
    __syncthreads();
    float denom = fmaxf(sqrtf(ws[0] + ws[1] + ws[2] + ws[3]), 1e-12f);
    float n[4] = {v.x / denom, v.y / denom, v.z / denom, v.w / denom};
    float* p = g_xv + (size_t)row * VK;
    #pragma unroll
    for (int i = 0; i < 4; i++) {
        float hi = tf32r(n[i]);
        float lo = tf32r(n[i] - hi);
        int sp = st_perm(e0 + i);
        p[sp] = hi; p[512 + sp] = lo; p[1024 + sp] = hi;
    }
}

// normalize codebook + split -> g_cv [hi|hi|lo] permuted, cnn
__global__ void norm_split_cb_kernel(const float* __restrict__ CB) {
    const int row = blockIdx.x;
    const int e0 = threadIdx.x * 4;
    float4 v = *(const float4*)(CB + (size_t)row * E_DIM + e0);
    float s = v.x * v.x + v.y * v.y + v.z * v.z + v.w * v.w;
    #pragma unroll
    for (int o = 16; o > 0; o >>= 1) s += __shfl_xor_sync(0xFFFFFFFFu, s, o);
    __shared__ float ws[4], ws2[4];
    if ((threadIdx.x & 31) == 0) ws[threadIdx.x >> 5] = s;
    __syncthreads();
    float denom = fmaxf(sqrtf(ws[0] + ws[1] + ws[2] + ws[3]), 1e-12f);
    float n[4] = {v.x / denom, v.y / denom, v.z / denom, v.w / denom};
    float* p = g_cv + (size_t)row * VK;
    #pragma unroll
    for (int i = 0; i < 4; i++) {
        float hi = tf32r(n[i]);
        float lo = tf32r(n[i] - hi);
        int sp = st_perm(e0 + i);
        p[sp] = hi; p[512 + sp] = hi; p[1024 + sp] = lo;
    }
    float s2 = n[0] * n[0] + n[1] * n[1] + n[2] * n[2] + n[3] * n[3];
    #pragma unroll
    for (int o = 16; o > 0; o >>= 1) s2 += __shfl_xor_sync(0xFFFFFFFFu, s2, o);
    if ((threadIdx.x & 31) == 0) ws2[threadIdx.x >> 5] = s2;
    __syncthreads();
    if (threadIdx.x == 0) g_cnn[row] = ws2[0] + ws2[1] + ws2[2] + ws2[3];
}

// ---------------------------------------------------------------------------
// mma.sync tf32 argmin: 128 q/block, 128 blocks (single wave), 512 threads.
// 16 warps = 4 q-warps x 4 k-warps; warp tile m32 x n64.
// Flat cp.async pipeline over 768 slices (16 chunks x 48 slices of 32 ve).
// ---------------------------------------------------------------------------
#define PIT 36                       // smem pitch (words) per 32-e row
#define XS_BUF (128 * PIT)           // 4608
#define BS_BUF (256 * PIT)           // 9216
#define SM_CNN (2 * XS_BUF + 2 * BS_BUF)       // 27648
#define SM_RV  (SM_CNN + K_CB)                  // 31744
#define SM_RI  (SM_RV + 512)                    // 32256
#define SMEM_TC ((SM_RI + 512) * 4)             // 131072 B

__global__ void __launch_bounds__(512, 1) tc_argmin_kernel(float* __restrict__ out) {
    extern __shared__ float sm[];
    float* xs    = sm;
    float* bs    = sm + 2 * XS_BUF;
    float* cnn_s = sm + SM_CNN;
    float* rv    = sm + SM_RV;
    int*   ri    = (int*)(sm + SM_RI);

    const int tid  = threadIdx.x;
    const int lane = tid & 31;
    const int w    = tid >> 5;
    const int kw   = w & 3;            // k-warp: 64 k each
    const int qw   = w >> 2;           // q-warp: 32 q each
    const int qb   = qw * 32;
    const int kb   = kw * 64;
    const int gr   = lane >> 2;        // 0..7
    const int gc2  = (lane & 3) * 2;   // 0,2,4,6
    const int q0   = blockIdx.x * 128;
    const uint32_t sbase = (uint32_t)__cvta_generic_to_shared(sm);

    #pragma unroll
    for (int t = 0; t < 8; t++) cnn_s[tid + t * 512] = g_cnn[tid + t * 512];

    // cp.async task split
    const int arow = tid >> 2, ac = (tid & 3) * 2;   // A: 128r x 8c float4, 2/thr
    const int brow = tid >> 1, bc = (tid & 1) * 4;   // B: 256r x 8c float4, 4/thr

    // prologue: slice 0 -> buf 0
    {
        #pragma unroll
        for (int t = 0; t < 2; t++)
            cp_async16(sbase + (arow * PIT + (ac + t) * 4) * 4,
                       g_xv + (size_t)(q0 + arow) * VK + (ac + t) * 4);
        #pragma unroll
        for (int t = 0; t < 4; t++)
            cp_async16(sbase + (2 * XS_BUF + brow * PIT + (bc + t) * 4) * 4,
                       g_cv + (size_t)brow * VK + (bc + t) * 4);
        cp_commit();
    }

    float acc[2][8][4];
    #pragma unroll
    for (int t = 0; t < 2; t++)
        #pragma unroll
        for (int j = 0; j < 8; j++)
            #pragma unroll
            for (int c = 0; c < 4; c++) acc[t][j][c] = 0.0f;

    float bv[4] = {-INFINITY, -INFINITY, -INFINITY, -INFINITY};
    int   bix[4] = {0, 0, 0, 0};

    for (int g = 0; g < GTOT; g++) {
        cp_wait<0>();
        __syncthreads();

        if (g + 1 < GTOT) {
            int ng = g + 1, nb = ng & 1;
            int nkc = (ng / NSL) * 256;
            size_t ne = (size_t)(ng % NSL) * 32;
            #pragma unroll
            for (int t = 0; t < 2; t++)
                cp_async16(sbase + (nb * XS_BUF + arow * PIT + (ac + t) * 4) * 4,
                           g_xv + (size_t)(q0 + arow) * VK + ne + (ac + t) * 4);
            #pragma unroll
            for (int t = 0; t < 4; t++)
                cp_async16(sbase + (2 * XS_BUF + nb * BS_BUF + brow * PIT + (bc + t) * 4) * 4,
                           g_cv + (size_t)(nkc + brow) * VK + ne + (bc + t) * 4);
            cp_commit();
        }

        const float* xa = xs + (g & 1) * XS_BUF;
        const float* bb = bs + (g & 1) * BS_BUF;
        #pragma unroll
        for (int s = 0; s < 4; s++) {
            const int e8 = s * 8 + gc2;
            float2 a00 = *(const float2*)(xa + (qb + gr) * PIT + e8);
            float2 a01 = *(const float2*)(xa + (qb + 8 + gr) * PIT + e8);
            float2 a10 = *(const float2*)(xa + (qb + 16 + gr) * PIT + e8);
            float2 a11 = *(const float2*)(xa + (qb + 24 + gr) * PIT + e8);
            uint32_t A0[4] = {__float_as_uint(a00.x), __float_as_uint(a01.x),
                              __float_as_uint(a00.y), __float_as_uint(a01.y)};
            uint32_t A1[4] = {__float_as_uint(a10.x), __float_as_uint(a11.x),
                              __float_as_uint(a10.y), __float_as_uint(a11.y)};
            #pragma unroll
            for (int j = 0; j < 8; j++) {
                float2 bf = *(const float2*)(bb + (kb + j * 8 + gr) * PIT + e8);
                uint32_t b0 = __float_as_uint(bf.x), b1 = __float_as_uint(bf.y);
                mma_tf32(acc[0][j], A0[0], A0[1], A0[2], A0[3], b0, b1);
                mma_tf32(acc[1][j], A1[0], A1[1], A1[2], A1[3], b0, b1);
            }
        }

        if ((g % NSL) == NSL - 1) {   // chunk done: score + reset
            const int kc = (g / NSL) * 256;
            #pragma unroll
            for (int t = 0; t < 2; t++)
                #pragma unroll
                for (int j = 0; j < 8; j++)
                    #pragma unroll
                    for (int c = 0; c < 4; c++) {
                        int k = kc + kb + j * 8 + gc2 + (c & 1);
                        float sc = acc[t][j][c] - 0.5f * cnn_s[k];
                        int bslot = t * 2 + (c >> 1);
                        if (sc > bv[bslot]) { bv[bslot] = sc; bix[bslot] = k; }
                        acc[t][j][c] = 0.0f;
                    }
        }
    }

    // reduce lanes sharing same q (xor 1,2 over lane&3), then across k-warps
    #pragma unroll
    for (int tb = 0; tb < 4; tb++) {
        float v = bv[tb]; int ix = bix[tb];
        #pragma unroll
        for (int o = 1; o <= 2; o <<= 1) {
            float ov = __shfl_xor_sync(0xFFFFFFFFu, v, o);
            int   oi = __shfl_xor_sync(0xFFFFFFFFu, ix, o);
            if (ov > v || (ov == v && oi < ix)) { v = ov; ix = oi; }
        }
        if ((lane & 3) == 0) {
            int q = qb + (tb >> 1) * 16 + (tb & 1) * 8 + gr;
            rv[q * 4 + kw] = v; ri[q * 4 + kw] = ix;
        }
    }
    __syncthreads();
    if (tid < 128) {
        float v = rv[tid * 4]; int ix = ri[tid * 4];
        #pragma unroll
        for (int t = 1; t < 4; t++) {
            float ov = rv[tid * 4 + t]; int oi = ri[tid * 4 + t];
            if (ov > v || (ov == v && oi < ix)) { v = ov; ix = oi; }
        }
        out[q0 + tid] = (float)ix;
    }
}

// ---------------------------------------------------------------------------
extern "C" void kernel_launch(void* const* d_in, const int* in_sizes, int n_in,
                              void* d_out, int out_size) {
    const float* x  = nullptr;
    const float* w  = nullptr;
    const float* cb = nullptr;
    for (int i = 0; i < n_in; i++) {
        if (in_sizes[i] == M_TOT * D_IN)       x  = (const float*)d_in[i];
        else if (in_sizes[i] == D_IN * E_DIM)  w  = (const float*)d_in[i];
        else if (in_sizes[i] == K_CB * E_DIM)  cb = (const float*)d_in[i];
    }
    float* out = (float*)d_out;

    dim3 g1(E_DIM / 64, M_TOT / 128);
    proj_gemm_kernel<<<g1, 256>>>(x, w);
    norm_split_x_kernel<<<M_TOT, 128>>>();
    norm_split_cb_kernel<<<K_CB, 128>>>(cb);

    cudaFuncSetAttribute(tc_argmin_kernel,
                         cudaFuncAttributeMaxDynamicSharedMemorySize, SMEM_TC);
    tc_argmin_kernel<<<M_TOT / 128, 512, SMEM_TC>>>(out);
}

// round 16
// speedup vs baseline: 1.0792x; 1.0792x over previous
#include <cuda_runtime.h>
#include <cstdint>
#include <cfloat>
#include <math.h>

#define M_TOT 16384
#define D_IN  1024
#define E_DIM 512
#define K_CB  4096
#define VK    1536              // 3 x 512 virtual contraction (3xTF32)
#define NSL   48                // 32-e slices per chunk
#define NCHUNK 16               // k chunks of 256
#define GTOT  (NCHUNK * NSL)    // 768

__device__ float g_xn[M_TOT * E_DIM];
__device__ float g_xv[(size_t)M_TOT * VK];   // [hi|lo|hi], fragment-permuted
__device__ float g_cv[(size_t)K_CB * VK];    // [hi|hi|lo], fragment-permuted
__device__ float g_cnn[K_CB];

// ---- helpers ----
__device__ __forceinline__ void cp_async16(uint32_t s, const void* g) {
    asm volatile("cp.async.cg.shared.global [%0], [%1], 16;" :: "r"(s), "l"(g) : "memory");
}
__device__ __forceinline__ void cp_commit() {
    asm volatile("cp.async.commit_group;" ::: "memory");
}
template <int N> __device__ __forceinline__ void cp_wait() {
    asm volatile("cp.async.wait_group %0;" :: "n"(N) : "memory");
}
__device__ __forceinline__ float tf32r(float x) {
    uint32_t r; asm("cvt.rna.tf32.f32 %0, %1;" : "=r"(r) : "f"(x));
    return __uint_as_float(r);
}
// within-32 fragment permutation: lane (e&3) gets its 4 k-steps contiguous
__device__ __forceinline__ int st_perm(int e) {
    int e5 = e & 31;
    return (e & ~31) + (e5 & 3) * 8 + (e5 >> 3) * 2 + ((e5 >> 2) & 1);
}
__device__ __forceinline__ void mma_tf32(float* c, uint32_t a0, uint32_t a1,
                                         uint32_t a2, uint32_t a3,
                                         uint32_t b0, uint32_t b1) {
    asm volatile("mma.sync.aligned.m16n8k8.row.col.f32.tf32.tf32.f32 "
                 "{%0,%1,%2,%3}, {%4,%5,%6,%7}, {%8,%9}, {%0,%1,%2,%3};"
                 : "+f"(c[0]), "+f"(c[1]), "+f"(c[2]), "+f"(c[3])
                 : "r"(a0), "r"(a1), "r"(a2), "r"(a3), "r"(b0), "r"(b1));
}
#define FU __float_as_uint

// ---------------------------------------------------------------------------
// Kernel 1: projection GEMM (known-good scalar, R11)
// ---------------------------------------------------------------------------
__global__ void proj_gemm_kernel(const float* __restrict__ X, const float* __restrict__ W) {
    __shared__ float As[32 * 132];
    __shared__ float Bs[32 * 64];
    const int tx = threadIdx.x & 15, ty = threadIdx.x >> 4;
    const int m0 = blockIdx.y * 128, n0 = blockIdx.x * 64;
    float acc[8][4];
    #pragma unroll
    for (int i = 0; i < 8; i++)
        #pragma unroll
        for (int j = 0; j < 4; j++) acc[i][j] = 0.0f;
    for (int kt = 0; kt < D_IN; kt += 32) {
        #pragma unroll
        for (int t = 0; t < 4; t++) {
            int f = threadIdx.x + t * 256, row = f >> 3, c4 = f & 7;
            float4 v = *(const float4*)(X + (size_t)(m0 + row) * D_IN + kt + c4 * 4);
            As[(c4 * 4 + 0) * 132 + row] = v.x; As[(c4 * 4 + 1) * 132 + row] = v.y;
            As[(c4 * 4 + 2) * 132 + row] = v.z; As[(c4 * 4 + 3) * 132 + row] = v.w;
        }
        #pragma unroll
        for (int t = 0; t < 2; t++) {
            int f = threadIdx.x + t * 256, k = f >> 4, c4 = f & 15;
            *(float4*)(Bs + k * 64 + c4 * 4) =
                *(const float4*)(W + (size_t)(kt + k) * E_DIM + n0 + c4 * 4);
        }
        __syncthreads();
        #pragma unroll
        for (int k = 0; k < 32; k++) {
            float4 a0 = *(const float4*)(As + k * 132 + ty * 8);
            float4 a1 = *(const float4*)(As + k * 132 + ty * 8 + 4);
            float4 b  = *(const float4*)(Bs + k * 64 + tx * 4);
            float a[8] = {a0.x, a0.y, a0.z, a0.w, a1.x, a1.y, a1.z, a1.w};
            float bb[4] = {b.x, b.y, b.z, b.w};
            #pragma unroll
            for (int i = 0; i < 8; i++)
                #pragma unroll
                for (int j = 0; j < 4; j++) acc[i][j] = fmaf(a[i], bb[j], acc[i][j]);
        }
        __syncthreads();
    }
    #pragma unroll
    for (int i = 0; i < 8; i++)
        *(float4*)(g_xn + (size_t)(m0 + ty * 8 + i) * E_DIM + n0 + tx * 4) =
            make_float4(acc[i][0], acc[i][1], acc[i][2], acc[i][3]);
}

// normalize x + 3xTF32 split -> g_xv [hi|lo|hi], fragment-permuted
__global__ void norm_split_x_kernel() {
    const int row = blockIdx.x;
    const int e0 = threadIdx.x * 4;
    float4 v = *(const float4*)(g_xn + (size_t)row * E_DIM + e0);
    float s = v.x * v.x + v.y * v.y + v.z * v.z + v.w * v.w;
    #pragma unroll
    for (int o = 16; o > 0; o >>= 1) s += __shfl_xor_sync(0xFFFFFFFFu, s, o);
    __shared__ float ws[4];
    if ((threadIdx.x & 31) == 0) ws[threadIdx.x >> 5] = s;
    __syncthreads();
    float denom = fmaxf(sqrtf(ws[0] + ws[1] + ws[2] + ws[3]), 1e-12f);
    float n[4] = {v.x / denom, v.y / denom, v.z / denom, v.w / denom};
    float* p = g_xv + (size_t)row * VK;
    #pragma unroll
    for (int i = 0; i < 4; i++) {
        float hi = tf32r(n[i]);
        float lo = tf32r(n[i] - hi);
        int sp = st_perm(e0 + i);
        p[sp] = hi; p[512 + sp] = lo; p[1024 + sp] = hi;
    }
}

// normalize codebook + split -> g_cv [hi|hi|lo] fragment-permuted, cnn
__global__ void norm_split_cb_kernel(const float* __restrict__ CB) {
    const int row = blockIdx.x;
    const int e0 = threadIdx.x * 4;
    float4 v = *(const float4*)(CB + (size_t)row * E_DIM + e0);
    float s = v.x * v.x + v.y * v.y + v.z * v.z + v.w * v.w;
    #pragma unroll
    for (int o = 16; o > 0; o >>= 1) s += __shfl_xor_sync(0xFFFFFFFFu, s, o);
    __shared__ float ws[4], ws2[4];
    if ((threadIdx.x & 31) == 0) ws[threadIdx.x >> 5] = s;
    __syncthreads();
    float denom = fmaxf(sqrtf(ws[0] + ws[1] + ws[2] + ws[3]), 1e-12f);
    float n[4] = {v.x / denom, v.y / denom, v.z / denom, v.w / denom};
    float* p = g_cv + (size_t)row * VK;
    #pragma unroll
    for (int i = 0; i < 4; i++) {
        float hi = tf32r(n[i]);
        float lo = tf32r(n[i] - hi);
        int sp = st_perm(e0 + i);
        p[sp] = hi; p[512 + sp] = hi; p[1024 + sp] = lo;
    }
    float s2 = n[0] * n[0] + n[1] * n[1] + n[2] * n[2] + n[3] * n[3];
    #pragma unroll
    for (int o = 16; o > 0; o >>= 1) s2 += __shfl_xor_sync(0xFFFFFFFFu, s2, o);
    if ((threadIdx.x & 31) == 0) ws2[threadIdx.x >> 5] = s2;
    __syncthreads();
    if (threadIdx.x == 0) g_cnn[row] = ws2[0] + ws2[1] + ws2[2] + ws2[3];
}

// ---------------------------------------------------------------------------
// mma.sync tf32 argmin: 128 q/block, 128 blocks (single wave), 512 threads.
// 16 warps = 4 q-warps x 4 k-warps; warp tile m32 x n64.
// A fragments (4 rows x 2 float4) held in regs per slice; B streamed 2 float4
// per j feeding 8 HMMAs. 24 LDS.128 per 64 HMMA per slice.
// ---------------------------------------------------------------------------
#define PIT 36
#define XS_BUF (128 * PIT)
#define BS_BUF (256 * PIT)
#define SM_CNN (2 * XS_BUF + 2 * BS_BUF)
#define SM_RV  (SM_CNN + K_CB)
#define SM_RI  (SM_RV + 512)
#define SMEM_TC ((SM_RI + 512) * 4)

__global__ void __launch_bounds__(512, 1) tc_argmin_kernel(float* __restrict__ out) {
    extern __shared__ float sm[];
    float* xs    = sm;
    float* bs    = sm + 2 * XS_BUF;
    float* cnn_s = sm + SM_CNN;
    float* rv    = sm + SM_RV;
    int*   ri    = (int*)(sm + SM_RI);

    const int tid  = threadIdx.x;
    const int lane = tid & 31;
    const int w    = tid >> 5;
    const int kw   = w & 3;
    const int qw   = w >> 2;
    const int qb   = qw * 32;
    const int kb   = kw * 64;
    const int gr   = lane >> 2;        // 0..7
    const int ps   = lane & 3;         // fragment pair-slot
    const int gc2  = ps * 2;
    const int q0   = blockIdx.x * 128;
    const uint32_t sbase = (uint32_t)__cvta_generic_to_shared(sm);

    #pragma unroll
    for (int t = 0; t < 8; t++) cnn_s[tid + t * 512] = g_cnn[tid + t * 512];

    const int arow = tid >> 2, ac = (tid & 3) * 2;   // A: 2 float4/thr
    const int brow = tid >> 1, bc = (tid & 1) * 4;   // B: 4 float4/thr

    // prologue: slice 0 -> buf 0
    {
        #pragma unroll
        for (int t = 0; t < 2; t++)
            cp_async16(sbase + (arow * PIT + (ac + t) * 4) * 4,
                       g_xv + (size_t)(q0 + arow) * VK + (ac + t) * 4);
        #pragma unroll
        for (int t = 0; t < 4; t++)
            cp_async16(sbase + (2 * XS_BUF + brow * PIT + (bc + t) * 4) * 4,
                       g_cv + (size_t)brow * VK + (bc + t) * 4);
        cp_commit();
    }

    float acc[2][8][4];
    #pragma unroll
    for (int t = 0; t < 2; t++)
        #pragma unroll
        for (int j = 0; j < 8; j++)
            #pragma unroll
            for (int c = 0; c < 4; c++) acc[t][j][c] = 0.0f;

    float bv[4] = {-INFINITY, -INFINITY, -INFINITY, -INFINITY};
    int   bix[4] = {0, 0, 0, 0};

    for (int g = 0; g < GTOT; g++) {
        cp_wait<0>();
        __syncthreads();

        if (g + 1 < GTOT) {
            int ng = g + 1, nb = ng & 1;
            int nkc = (ng / NSL) * 256;
            size_t ne = (size_t)(ng % NSL) * 32;
            #pragma unroll
            for (int t = 0; t < 2; t++)
                cp_async16(sbase + (nb * XS_BUF + arow * PIT + (ac + t) * 4) * 4,
                           g_xv + (size_t)(q0 + arow) * VK + ne + (ac + t) * 4);
            #pragma unroll
            for (int t = 0; t < 4; t++)
                cp_async16(sbase + (2 * XS_BUF + nb * BS_BUF + brow * PIT + (bc + t) * 4) * 4,
                           g_cv + (size_t)(nkc + brow) * VK + ne + (bc + t) * 4);
            cp_commit();
        }

        const float* xa = xs + (g & 1) * XS_BUF;
        const float* bb = bs + (g & 1) * BS_BUF;

        // A fragments: 4 rows x 8 contiguous words (all 4 k-steps)
        float4 A_f[4][2];
        #pragma unroll
        for (int r = 0; r < 4; r++) {
            const float* ap = xa + (qb + r * 8 + gr) * PIT + ps * 8;
            A_f[r][0] = *(const float4*)(ap);
            A_f[r][1] = *(const float4*)(ap + 4);
        }

        #pragma unroll
        for (int j = 0; j < 8; j++) {
            const float* bp = bb + (kb + j * 8 + gr) * PIT + ps * 8;
            float4 B0 = *(const float4*)(bp);
            float4 B1 = *(const float4*)(bp + 4);
            // s=0: lo=f0.x hi=f0.y ; s=1: f0.z/w ; s=2: f1.x/y ; s=3: f1.z/w
            mma_tf32(acc[0][j], FU(A_f[0][0].x), FU(A_f[1][0].x), FU(A_f[0][0].y), FU(A_f[1][0].y), FU(B0.x), FU(B0.y));
            mma_tf32(acc[1][j], FU(A_f[2][0].x), FU(A_f[3][0].x), FU(A_f[2][0].y), FU(A_f[3][0].y), FU(B0.x), FU(B0.y));
            mma_tf32(acc[0][j], FU(A_f[0][0].z), FU(A_f[1][0].z), FU(A_f[0][0].w), FU(A_f[1][0].w), FU(B0.z), FU(B0.w));
            mma_tf32(acc[1][j], FU(A_f[2][0].z), FU(A_f[3][0].z), FU(A_f[2][0].w), FU(A_f[3][0].w), FU(B0.z), FU(B0.w));
            mma_tf32(acc[0][j], FU(A_f[0][1].x), FU(A_f[1][1].x), FU(A_f[0][1].y), FU(A_f[1][1].y), FU(B1.x), FU(B1.y));
            mma_tf32(acc[1][j], FU(A_f[2][1].x), FU(A_f[3][1].x), FU(A_f[2][1].y), FU(A_f[3][1].y), FU(B1.x), FU(B1.y));
            mma_tf32(acc[0][j], FU(A_f[0][1].z), FU(A_f[1][1].z), FU(A_f[0][1].w), FU(A_f[1][1].w), FU(B1.z), FU(B1.w));
            mma_tf32(acc[1][j], FU(A_f[2][1].z), FU(A_f[3][1].z), FU(A_f[2][1].w), FU(A_f[3][1].w), FU(B1.z), FU(B1.w));
        }

        if ((g % NSL) == NSL - 1) {   // chunk done: score + reset
            const int kc = (g / NSL) * 256;
            #pragma unroll
            for (int t = 0; t < 2; t++)
                #pragma unroll
                for (int j = 0; j < 8; j++)
                    #pragma unroll
                    for (int c = 0; c < 4; c++) {
                        int k = kc + kb + j * 8 + gc2 + (c & 1);
                        float sc = acc[t][j][c] - 0.5f * cnn_s[k];
                        int bslot = t * 2 + (c >> 1);
                        if (sc > bv[bslot]) { bv[bslot] = sc; bix[bslot] = k; }
                        acc[t][j][c] = 0.0f;
                    }
        }
    }

    // reduce lanes sharing same q, then across k-warps
    #pragma unroll
    for (int tb = 0; tb < 4; tb++) {
        float v = bv[tb]; int ix = bix[tb];
        #pragma unroll
        for (int o = 1; o <= 2; o <<= 1) {
            float ov = __shfl_xor_sync(0xFFFFFFFFu, v, o);
            int   oi = __shfl_xor_sync(0xFFFFFFFFu, ix, o);
            if (ov > v || (ov == v && oi < ix)) { v = ov; ix = oi; }
        }
        if ((lane & 3) == 0) {
            int q = qb + (tb >> 1) * 16 + (tb & 1) * 8 + gr;
            rv[q * 4 + kw] = v; ri[q * 4 + kw] = ix;
        }
    }
    __syncthreads();
    if (tid < 128) {
        float v = rv[tid * 4]; int ix = ri[tid * 4];
        #pragma unroll
        for (int t = 1; t < 4; t++) {
            float ov = rv[tid * 4 + t]; int oi = ri[tid * 4 + t];
            if (ov > v || (ov == v && oi < ix)) { v = ov; ix = oi; }
        }
        out[q0 + tid] = (float)ix;
    }
}

// ---------------------------------------------------------------------------
extern "C" void kernel_launch(void* const* d_in, const int* in_sizes, int n_in,
                              void* d_out, int out_size) {
    const float* x  = nullptr;
    const float* w  = nullptr;
    const float* cb = nullptr;
    for (int i = 0; i < n_in; i++) {
        if (in_sizes[i] == M_TOT * D_IN)       x  = (const float*)d_in[i];
        else if (in_sizes[i] == D_IN * E_DIM)  w  = (const float*)d_in[i];
        else if (in_sizes[i] == K_CB * E_DIM)  cb = (const float*)d_in[i];
    }
    float* out = (float*)d_out;

    dim3 g1(E_DIM / 64, M_TOT / 128);
    proj_gemm_kernel<<<g1, 256>>>(x, w);
    norm_split_x_kernel<<<M_TOT, 128>>>();
    norm_split_cb_kernel<<<K_CB, 128>>>(cb);

    cudaFuncSetAttribute(tc_argmin_kernel,
                         cudaFuncAttributeMaxDynamicSharedMemorySize, SMEM_TC);
    tc_argmin_kernel<<<M_TOT / 128, 512, SMEM_TC>>>(out);
}

// round 17
// speedup vs baseline: 2.1072x; 1.9525x over previous
#include <cuda_runtime.h>
#include <cuda_fp16.h>
#include <cstdint>
#include <cfloat>
#include <math.h>

#define M_TOT 16384
#define D_IN  1024
#define E_DIM 512
#define K_CB  4096
#define VK    512               // 1 x TF32
#define NSL   16                // 32-e slices per chunk
#define NCHUNK 16               // k chunks of 256
#define GTOT  (NCHUNK * NSL)    // 256
#define DELTA 4e-3f
#define CAP   32

__device__ float g_xn[M_TOT * E_DIM];        // normalized queries (fp32)
__device__ float g_cn[K_CB * E_DIM];         // normalized codebook (fp32)
__device__ float g_xv[(size_t)M_TOT * VK];   // tf32(xn), fragment-permuted
__device__ float g_cv[(size_t)K_CB * VK];    // tf32(cn), fragment-permuted
__device__ float g_cnn[K_CB];
__device__ __half g_scores[(size_t)M_TOT * K_CB];   // approx scores

// ---- helpers ----
__device__ __forceinline__ void cp_async16(uint32_t s, const void* g) {
    asm volatile("cp.async.cg.shared.global [%0], [%1], 16;" :: "r"(s), "l"(g) : "memory");
}
__device__ __forceinline__ void cp_commit() {
    asm volatile("cp.async.commit_group;" ::: "memory");
}
template <int N> __device__ __forceinline__ void cp_wait() {
    asm volatile("cp.async.wait_group %0;" :: "n"(N) : "memory");
}
__device__ __forceinline__ float tf32r(float x) {
    uint32_t r; asm("cvt.rna.tf32.f32 %0, %1;" : "=r"(r) : "f"(x));
    return __uint_as_float(r);
}
// within-32 fragment permutation (proven in R16)
__device__ __forceinline__ int st_perm(int e) {
    int e5 = e & 31;
    return (e & ~31) + (e5 & 3) * 8 + (e5 >> 3) * 2 + ((e5 >> 2) & 1);
}
__device__ __forceinline__ void mma_tf32(float* c, uint32_t a0, uint32_t a1,
                                         uint32_t a2, uint32_t a3,
                                         uint32_t b0, uint32_t b1) {
    asm volatile("mma.sync.aligned.m16n8k8.row.col.f32.tf32.tf32.f32 "
                 "{%0,%1,%2,%3}, {%4,%5,%6,%7}, {%8,%9}, {%0,%1,%2,%3};"
                 : "+f"(c[0]), "+f"(c[1]), "+f"(c[2]), "+f"(c[3])
                 : "r"(a0), "r"(a1), "r"(a2), "r"(a3), "r"(b0), "r"(b1));
}
#define FU __float_as_uint

// ---------------------------------------------------------------------------
// Kernel 1: projection GEMM (known-good scalar)
// ---------------------------------------------------------------------------
__global__ void proj_gemm_kernel(const float* __restrict__ X, const float* __restrict__ W) {
    __shared__ float As[32 * 132];
    __shared__ float Bs[32 * 64];
    const int tx = threadIdx.x & 15, ty = threadIdx.x >> 4;
    const int m0 = blockIdx.y * 128, n0 = blockIdx.x * 64;
    float acc[8][4];
    #pragma unroll
    for (int i = 0; i < 8; i++)
        #pragma unroll
        for (int j = 0; j < 4; j++) acc[i][j] = 0.0f;
    for (int kt = 0; kt < D_IN; kt += 32) {
        #pragma unroll
        for (int t = 0; t < 4; t++) {
            int f = threadIdx.x + t * 256, row = f >> 3, c4 = f & 7;
            float4 v = *(const float4*)(X + (size_t)(m0 + row) * D_IN + kt + c4 * 4);
            As[(c4 * 4 + 0) * 132 + row] = v.x; As[(c4 * 4 + 1) * 132 + row] = v.y;
            As[(c4 * 4 + 2) * 132 + row] = v.z; As[(c4 * 4 + 3) * 132 + row] = v.w;
        }
        #pragma unroll
        for (int t = 0; t < 2; t++) {
            int f = threadIdx.x + t * 256, k = f >> 4, c4 = f & 15;
            *(float4*)(Bs + k * 64 + c4 * 4) =
                *(const float4*)(W + (size_t)(kt + k) * E_DIM + n0 + c4 * 4);
        }
        __syncthreads();
        #pragma unroll
        for (int k = 0; k < 32; k++) {
            float4 a0 = *(const float4*)(As + k * 132 + ty * 8);
            float4 a1 = *(const float4*)(As + k * 132 + ty * 8 + 4);
            float4 b  = *(const float4*)(Bs + k * 64 + tx * 4);
            float a[8] = {a0.x, a0.y, a0.z, a0.w, a1.x, a1.y, a1.z, a1.w};
            float bb[4] = {b.x, b.y, b.z, b.w};
            #pragma unroll
            for (int i = 0; i < 8; i++)
                #pragma unroll
                for (int j = 0; j < 4; j++) acc[i][j] = fmaf(a[i], bb[j], acc[i][j]);
        }
        __syncthreads();
    }
    #pragma unroll
    for (int i = 0; i < 8; i++)
        *(float4*)(g_xn + (size_t)(m0 + ty * 8 + i) * E_DIM + n0 + tx * 4) =
            make_float4(acc[i][0], acc[i][1], acc[i][2], acc[i][3]);
}

// normalize x in place + tf32 copy -> g_xv (permuted)
__global__ void norm_split_x_kernel() {
    const int row = blockIdx.x;
    const int e0 = threadIdx.x * 4;
    float4 v = *(const float4*)(g_xn + (size_t)row * E_DIM + e0);
    float s = v.x * v.x + v.y * v.y + v.z * v.z + v.w * v.w;
    #pragma unroll
    for (int o = 16; o > 0; o >>= 1) s += __shfl_xor_sync(0xFFFFFFFFu, s, o);
    __shared__ float ws[4];
    if ((threadIdx.x & 31) == 0) ws[threadIdx.x >> 5] = s;
    __syncthreads();
    float denom = fmaxf(sqrtf(ws[0] + ws[1] + ws[2] + ws[3]), 1e-12f);
    float n[4] = {v.x / denom, v.y / denom, v.z / denom, v.w / denom};
    *(float4*)(g_xn + (size_t)row * E_DIM + e0) = make_float4(n[0], n[1], n[2], n[3]);
    float* p = g_xv + (size_t)row * VK;
    #pragma unroll
    for (int i = 0; i < 4; i++) p[st_perm(e0 + i)] = tf32r(n[i]);
}

// normalize codebook -> g_cn (fp32), g_cv (tf32 permuted), g_cnn
__global__ void norm_split_cb_kernel(const float* __restrict__ CB) {
    const int row = blockIdx.x;
    const int e0 = threadIdx.x * 4;
    float4 v = *(const float4*)(CB + (size_t)row * E_DIM + e0);
    float s = v.x * v.x + v.y * v.y + v.z * v.z + v.w * v.w;
    #pragma unroll
    for (int o = 16; o > 0; o >>= 1) s += __shfl_xor_sync(0xFFFFFFFFu, s, o);
    __shared__ float ws[4], ws2[4];
    if ((threadIdx.x & 31) == 0) ws[threadIdx.x >> 5] = s;
    __syncthreads();
    float denom = fmaxf(sqrtf(ws[0] + ws[1] + ws[2] + ws[3]), 1e-12f);
    float n[4] = {v.x / denom, v.y / denom, v.z / denom, v.w / denom};
    *(float4*)(g_cn + (size_t)row * E_DIM + e0) = make_float4(n[0], n[1], n[2], n[3]);
    float* p = g_cv + (size_t)row * VK;
    #pragma unroll
    for (int i = 0; i < 4; i++) p[st_perm(e0 + i)] = tf32r(n[i]);
    float s2 = n[0] * n[0] + n[1] * n[1] + n[2] * n[2] + n[3] * n[3];
    #pragma unroll
    for (int o = 16; o > 0; o >>= 1) s2 += __shfl_xor_sync(0xFFFFFFFFu, s2, o);
    if ((threadIdx.x & 31) == 0) ws2[threadIdx.x >> 5] = s2;
    __syncthreads();
    if (threadIdx.x == 0) g_cnn[row] = ws2[0] + ws2[1] + ws2[2] + ws2[3];
}

// ---------------------------------------------------------------------------
// tf32 approx scores + candidate rescore. 128 q/block, 128 blocks, 512 thr.
// ---------------------------------------------------------------------------
#define PIT 36
#define XS_BUF (128 * PIT)                 // 4608 w
#define BS_BUF (256 * PIT)                 // 9216 w
#define SM_CNN (2 * XS_BUF + 2 * BS_BUF)   // 27648
#define SM_STG (SM_CNN + K_CB)             // 31744  staged scores [128][132] half2
#define SM_RV  (SM_STG + 128 * 132)        // 48640  per-(q,kw) maxes
#define SM_MQ  (SM_RV + 512)               // 49152  thresholds [128]
#define SM_CNT (SM_MQ + 128)               // 49280  cand counters [128]
#define SM_CAND (SM_CNT + 128)             // 49408  cand lists [128*CAP]
#define SMEM_TC ((SM_CAND + 128 * CAP) * 4)   // 214016 B

__global__ void __launch_bounds__(512, 1) tc_argmin_kernel(float* __restrict__ out) {
    extern __shared__ float sm[];
    float* xs    = sm;
    float* bs    = sm + 2 * XS_BUF;
    float* cnn_s = sm + SM_CNN;
    uint32_t* stg = (uint32_t*)(sm + SM_STG);   // half2 cells, pitch 132
    float* rv    = sm + SM_RV;
    float* thr   = sm + SM_MQ;
    int*   cnt   = (int*)(sm + SM_CNT);
    int*   cand  = (int*)(sm + SM_CAND);

    const int tid  = threadIdx.x;
    const int lane = tid & 31;
    const int w    = tid >> 5;
    const int kw   = w & 3;
    const int qw   = w >> 2;
    const int qb   = qw * 32;
    const int kb   = kw * 64;
    const int gr   = lane >> 2;
    const int ps   = lane & 3;
    const int q0   = blockIdx.x * 128;
    const uint32_t sbase = (uint32_t)__cvta_generic_to_shared(sm);

    #pragma unroll
    for (int t = 0; t < 8; t++) cnn_s[tid + t * 512] = g_cnn[tid + t * 512];

    const int arow = tid >> 2, ac = (tid & 3) * 2;
    const int brow = tid >> 1, bc = (tid & 1) * 4;

    // prologue: slice 0 -> buf 0
    #pragma unroll
    for (int t = 0; t < 2; t++)
        cp_async16(sbase + (arow * PIT + (ac + t) * 4) * 4,
                   g_xv + (size_t)(q0 + arow) * VK + (ac + t) * 4);
    #pragma unroll
    for (int t = 0; t < 4; t++)
        cp_async16(sbase + (2 * XS_BUF + brow * PIT + (bc + t) * 4) * 4,
                   g_cv + (size_t)brow * VK + (bc + t) * 4);
    cp_commit();

    float acc[2][8][4];
    #pragma unroll
    for (int t = 0; t < 2; t++)
        #pragma unroll
        for (int j = 0; j < 8; j++)
            #pragma unroll
            for (int c = 0; c < 4; c++) acc[t][j][c] = 0.0f;

    float bv[4] = {-INFINITY, -INFINITY, -INFINITY, -INFINITY};

    for (int g = 0; g < GTOT; g++) {
        cp_wait<0>();
        __syncthreads();

        if (g + 1 < GTOT) {
            int ng = g + 1, nb = ng & 1;
            int nkc = (ng / NSL) * 256;
            size_t ne = (size_t)(ng % NSL) * 32;
            #pragma unroll
            for (int t = 0; t < 2; t++)
                cp_async16(sbase + (nb * XS_BUF + arow * PIT + (ac + t) * 4) * 4,
                           g_xv + (size_t)(q0 + arow) * VK + ne + (ac + t) * 4);
            #pragma unroll
            for (int t = 0; t < 4; t++)
                cp_async16(sbase + (2 * XS_BUF + nb * BS_BUF + brow * PIT + (bc + t) * 4) * 4,
                           g_cv + (size_t)(nkc + brow) * VK + ne + (bc + t) * 4);
            cp_commit();
        }

        const float* xa = xs + (g & 1) * XS_BUF;
        const float* bb = bs + (g & 1) * BS_BUF;

        float4 A_f[4][2];
        #pragma unroll
        for (int r = 0; r < 4; r++) {
            const float* ap = xa + (qb + r * 8 + gr) * PIT + ps * 8;
            A_f[r][0] = *(const float4*)(ap);
            A_f[r][1] = *(const float4*)(ap + 4);
        }

        #pragma unroll
        for (int j = 0; j < 8; j++) {
            const float* bp = bb + (kb + j * 8 + gr) * PIT + ps * 8;
            float4 B0 = *(const float4*)(bp);
            float4 B1 = *(const float4*)(bp + 4);
            mma_tf32(acc[0][j], FU(A_f[0][0].x), FU(A_f[1][0].x), FU(A_f[0][0].y), FU(A_f[1][0].y), FU(B0.x), FU(B0.y));
            mma_tf32(acc[1][j], FU(A_f[2][0].x), FU(A_f[3][0].x), FU(A_f[2][0].y), FU(A_f[3][0].y), FU(B0.x), FU(B0.y));
            mma_tf32(acc[0][j], FU(A_f[0][0].z), FU(A_f[1][0].z), FU(A_f[0][0].w), FU(A_f[1][0].w), FU(B0.z), FU(B0.w));
            mma_tf32(acc[1][j], FU(A_f[2][0].z), FU(A_f[3][0].z), FU(A_f[2][0].w), FU(A_f[3][0].w), FU(B0.z), FU(B0.w));
            mma_tf32(acc[0][j], FU(A_f[0][1].x), FU(A_f[1][1].x), FU(A_f[0][1].y), FU(A_f[1][1].y), FU(B1.x), FU(B1.y));
            mma_tf32(acc[1][j], FU(A_f[2][1].x), FU(A_f[3][1].x), FU(A_f[2][1].y), FU(A_f[3][1].y), FU(B1.x), FU(B1.y));
            mma_tf32(acc[0][j], FU(A_f[0][1].z), FU(A_f[1][1].z), FU(A_f[0][1].w), FU(A_f[1][1].w), FU(B1.z), FU(B1.w));
            mma_tf32(acc[1][j], FU(A_f[2][1].z), FU(A_f[3][1].z), FU(A_f[2][1].w), FU(A_f[3][1].w), FU(B1.z), FU(B1.w));
        }

        if ((g % NSL) == NSL - 1) {   // chunk done: stage scores, dump, track max
            const int kc = (g / NSL) * 256;
            #pragma unroll
            for (int t = 0; t < 2; t++)
                #pragma unroll
                for (int j = 0; j < 8; j++) {
                    int k2 = (kb >> 1) + j * 4 + ps;   // half2 column
                    #pragma unroll
                    for (int h = 0; h < 2; h++) {
                        int q = qb + t * 16 + h * 8 + gr;
                        float s0 = acc[t][j][2 * h + 0] - 0.5f * cnn_s[kc + 2 * k2];
                        float s1 = acc[t][j][2 * h + 1] - 0.5f * cnn_s[kc + 2 * k2 + 1];
                        __half2 hh = __floats2half2_rn(s0, s1);
                        stg[q * 132 + k2] = *(uint32_t*)&hh;
                        float m = fmaxf(s0, s1);
                        int bslot = t * 2 + h;
                        if (m > bv[bslot]) bv[bslot] = m;
                        acc[t][j][2 * h + 0] = 0.0f;
                        acc[t][j][2 * h + 1] = 0.0f;
                    }
                }
            __syncthreads();
            // coalesced dump: 128 rows x 32 uint4
            #pragma unroll
            for (int i = 0; i < 8; i++) {
                int idx = tid + i * 512;
                int row = idx >> 5, c16 = idx & 31;
                uint4 v4 = *(uint4*)(stg + row * 132 + c16 * 4);
                *(uint4*)(g_scores + (size_t)(q0 + row) * K_CB + kc + c16 * 8) = v4;
            }
            __syncthreads();
        }
    }

    // per-q max across lanes and k-warps
    #pragma unroll
    for (int tb = 0; tb < 4; tb++) {
        float v = bv[tb];
        #pragma unroll
        for (int o = 1; o <= 2; o <<= 1)
            v = fmaxf(v, __shfl_xor_sync(0xFFFFFFFFu, v, o));
        if ((lane & 3) == 0) {
            int q = qb + (tb >> 1) * 16 + (tb & 1) * 8 + gr;
            rv[q * 4 + kw] = v;
        }
    }
    __syncthreads();
    if (tid < 128) {
        float m = fmaxf(fmaxf(rv[tid * 4], rv[tid * 4 + 1]),
                        fmaxf(rv[tid * 4 + 2], rv[tid * 4 + 3]));
        thr[tid] = m - DELTA;
        cnt[tid] = 0;
    }
    __syncthreads();

    // candidate scan: 4 threads per q, 1024 k each
    {
        const int q = tid >> 2, part = tid & 3;
        const float th = thr[q];
        const __half* srow = g_scores + (size_t)(q0 + q) * K_CB + part * 1024;
        for (int i = 0; i < 128; i++) {
            uint4 v4 = *(const uint4*)(srow + i * 8);
            uint32_t wd[4] = {v4.x, v4.y, v4.z, v4.w};
            #pragma unroll
            for (int p = 0; p < 4; p++) {
                float2 f = __half22float2(*(__half2*)&wd[p]);
                if (f.x >= th) {
                    int n = atomicAdd(&cnt[q], 1);
                    if (n < CAP) cand[q * CAP + n] = part * 1024 + i * 8 + p * 2;
                }
                if (f.y >= th) {
                    int n = atomicAdd(&cnt[q], 1);
                    if (n < CAP) cand[q * CAP + n] = part * 1024 + i * 8 + p * 2 + 1;
                }
            }
        }
    }
    __syncthreads();

    // exact fp32 rescore of candidates (4 threads per q)
    {
        const int q = tid >> 2, sub = tid & 3;
        const int n_raw = cnt[q];
        const bool overflow = (n_raw > CAP);
        const int n = overflow ? K_CB : n_raw;
        const float* xrow = g_xn + (size_t)(q0 + q) * E_DIM;
        float bvv = -INFINITY;
        int   bii = 0;
        for (int c = 0; c < n; c++) {
            int k = overflow ? c : cand[q * CAP + c];
            const float* crow = g_cn + (size_t)k * E_DIM + sub * 128;
            const float* xr   = xrow + sub * 128;
            float d = 0.0f;
            #pragma unroll 8
            for (int e4 = 0; e4 < 32; e4++) {
                float4 xv = *(const float4*)(xr + e4 * 4);
                float4 cv = *(const float4*)(crow + e4 * 4);
                d = fmaf(xv.x, cv.x, d); d = fmaf(xv.y, cv.y, d);
                d = fmaf(xv.z, cv.z, d); d = fmaf(xv.w, cv.w, d);
            }
            d += __shfl_xor_sync(0xFFFFFFFFu, d, 1);
            d += __shfl_xor_sync(0xFFFFFFFFu, d, 2);
            float sc = d - 0.5f * g_cnn[k];
            if (sc > bvv || (sc == bvv && k < bii)) { bvv = sc; bii = k; }
        }
        if (sub == 0) out[q0 + q] = (float)bii;
    }
}

// ---------------------------------------------------------------------------
extern "C" void kernel_launch(void* const* d_in, const int* in_sizes, int n_in,
                              void* d_out, int out_size) {
    const float* x  = nullptr;
    const float* w  = nullptr;
    const float* cb = nullptr;
    for (int i = 0; i < n_in; i++) {
        if (in_sizes[i] == M_TOT * D_IN)       x  = (const float*)d_in[i];
        else if (in_sizes[i] == D_IN * E_DIM)  w  = (const float*)d_in[i];
        else if (in_sizes[i] == K_CB * E_DIM)  cb = (const float*)d_in[i];
    }
    float* out = (float*)d_out;

    dim3 g1(E_DIM / 64, M_TOT / 128);
    proj_gemm_kernel<<<g1, 256>>>(x, w);
    norm_split_x_kernel<<<M_TOT, 128>>>();
    norm_split_cb_kernel<<<K_CB, 128>>>(cb);

    cudaFuncSetAttribute(tc_argmin_kernel,
                         cudaFuncAttributeMaxDynamicSharedMemorySize, SMEM_TC);
    tc_argmin_kernel<<<M_TOT / 128, 512, SMEM_TC>>>(out);
}